// round 10
// baseline (speedup 1.0000x reference)
#include <cuda_runtime.h>
#include <cstdint>

#define DIM     256
#define BT      32768
#define NCODE   2048
#define MARGIN  4.0f
#define RCAP    6                  // candidates per row per tile record
#define MBLK    128
#define NTILE   128
#define N_TILES (NCODE / NTILE)    // 16
#define N_KC    2                  // two 128-dim s8 chunks (128B rows)
#define STAGE_BYTES 32768          // A 16KB + B 16KB

// GEMM smem layout (relative to 1KB-aligned base)
#define OFF_BUF  0                 // 2 stages x 32 KB
#define OFF_KEY  65536             // u32[128]
#define OFF_CNT  66048             // int[128]
#define OFF_CAND 66560             // int[128][RCAP] = 3072
#define SMEM_BYTES (66560 + 128 * RCAP * 4 + 1024)

// ---------------------------------------------------------------------------
__device__ int8_t g_xq[(size_t)BT * DIM];       // 8 MB
__device__ int8_t g_cq[(size_t)NCODE * DIM];    // 512 KB
__device__ float  g_sx[BT];
__device__ float  g_sc[NCODE];
__device__ float  g_c2[NCODE];
__device__ int    g_rec[(size_t)BT * N_TILES * 8];  // 16 MB: {minf,cnt,cand[6]}
__device__ float  g_partial[BT];
__device__ float  g_dummy[BT + 1];

// ---------------------------------------------------------------------------
__device__ __forceinline__ uint32_t smem_u32(const void* p) {
    uint32_t a;
    asm("{ .reg .u64 t; cvta.to.shared.u64 t, %1; cvt.u32.u64 %0, t; }"
        : "=r"(a) : "l"(p));
    return a;
}

#define SWZ(o) ((o) ^ (((o) >> 3) & 0x70))

__device__ __forceinline__ void cp16(uint32_t d, const void* s) {
    asm volatile("cp.async.cg.shared.global [%0], [%1], 16;\n"
                 :: "r"(d), "l"(__cvta_generic_to_global(s)));
}
__device__ __forceinline__ void cp_commit() {
    asm volatile("cp.async.commit_group;\n" ::: "memory");
}
template <int N> __device__ __forceinline__ void cp_wait() {
    asm volatile("cp.async.wait_group %0;\n" :: "n"(N) : "memory");
}

__device__ __forceinline__ void ldm_x4(uint32_t& r0, uint32_t& r1,
                                       uint32_t& r2, uint32_t& r3, uint32_t a) {
    asm volatile("ldmatrix.sync.aligned.m8n8.x4.shared.b16 {%0,%1,%2,%3}, [%4];"
                 : "=r"(r0), "=r"(r1), "=r"(r2), "=r"(r3) : "r"(a));
}

// s8 x s8 -> s32, m16n8k32. Fragment bytes identical to bf16 m16n8k16 layout.
__device__ __forceinline__ void mma_s8(int32_t* d, uint32_t a0, uint32_t a1,
                                       uint32_t a2, uint32_t a3,
                                       uint32_t b0, uint32_t b1) {
    asm volatile(
        "mma.sync.aligned.m16n8k32.row.col.s32.s8.s8.s32 "
        "{%0,%1,%2,%3}, {%4,%5,%6,%7}, {%8,%9}, {%0,%1,%2,%3};"
        : "+r"(d[0]), "+r"(d[1]), "+r"(d[2]), "+r"(d[3])
        : "r"(a0), "r"(a1), "r"(a2), "r"(a3), "r"(b0), "r"(b1));
}

__device__ __forceinline__ uint32_t fkey(float f) {
    uint32_t u = __float_as_uint(f);
    return (u & 0x80000000u) ? ~u : (u | 0x80000000u);
}
__device__ __forceinline__ float fdec(uint32_t k) {
    uint32_t u = (k & 0x80000000u) ? (k ^ 0x80000000u) : ~k;
    return __uint_as_float(u);
}

// ---------------------------------------------------------------------------
// Quantize fp32 rows -> s8 rows + per-row scale. One warp per 256-dim row.
// ---------------------------------------------------------------------------
__device__ __forceinline__ int q8(float v, float inv) {
    int q = __float2int_rn(v * inv);
    return max(-127, min(127, q));
}

__global__ void quant_kernel(const float* __restrict__ in,
                             int8_t* __restrict__ outq,
                             float* __restrict__ scales, int nrows) {
    int row  = (blockIdx.x * blockDim.x + threadIdx.x) >> 5;
    int lane = threadIdx.x & 31;
    if (row >= nrows) return;
    const float4* r4 = (const float4*)(in + (size_t)row * DIM);
    float4 v0 = r4[lane * 2], v1 = r4[lane * 2 + 1];
    float m = fmaxf(fmaxf(fabsf(v0.x), fabsf(v0.y)),
                    fmaxf(fabsf(v0.z), fabsf(v0.w)));
    m = fmaxf(m, fmaxf(fmaxf(fabsf(v1.x), fabsf(v1.y)),
                       fmaxf(fabsf(v1.z), fabsf(v1.w))));
#pragma unroll
    for (int o = 16; o > 0; o >>= 1) m = fmaxf(m, __shfl_xor_sync(0xffffffffu, m, o));
    m = fmaxf(m, 1e-20f);
    float inv = 127.0f / m;
    if (lane == 0) scales[row] = m / 127.0f;
    uint32_t lo = (uint32_t)(q8(v0.x, inv) & 0xFF)
                | ((uint32_t)(q8(v0.y, inv) & 0xFF) << 8)
                | ((uint32_t)(q8(v0.z, inv) & 0xFF) << 16)
                | ((uint32_t)(q8(v0.w, inv) & 0xFF) << 24);
    uint32_t hi = (uint32_t)(q8(v1.x, inv) & 0xFF)
                | ((uint32_t)(q8(v1.y, inv) & 0xFF) << 8)
                | ((uint32_t)(q8(v1.z, inv) & 0xFF) << 16)
                | ((uint32_t)(q8(v1.w, inv) & 0xFF) << 24);
    ((uint2*)(outq + (size_t)row * DIM))[lane] = make_uint2(lo, hi);
}

__global__ void c2_kernel(const float* __restrict__ cb, int N) {
    int warp = (blockIdx.x * blockDim.x + threadIdx.x) >> 5;
    int lane = threadIdx.x & 31;
    if (warp >= N) return;
    const float4* row = (const float4*)(cb + (size_t)warp * DIM);
    float s = 0.f;
#pragma unroll
    for (int i = 0; i < 2; i++) {
        float4 v = row[lane + i * 32];
        s += v.x * v.x + v.y * v.y + v.z * v.z + v.w * v.w;
    }
#pragma unroll
    for (int o = 16; o > 0; o >>= 1) s += __shfl_xor_sync(0xffffffffu, s, o);
    if (lane == 0) g_c2[warp] = s;
}

// ---------------------------------------------------------------------------
// stage one s8 chunk: A[128 x 128B] + B[128 x 128B] (16KB each)
// ---------------------------------------------------------------------------
__device__ __forceinline__ void stage_ab(uint32_t dst, int m0, int n0,
                                         int kc, int tid) {
#pragma unroll
    for (int i = 0; i < 4; i++) {
        int idx = tid + (i << 8);
        int c16 = idx & 7;
        int row = idx >> 3;
        uint32_t off = SWZ((uint32_t)(row * 128 + c16 * 16));
        cp16(dst + off,
             g_xq + (size_t)(m0 + row) * DIM + kc * 128 + c16 * 16);
        cp16(dst + 16384 + off,
             g_cq + (size_t)(n0 + row) * DIM + kc * 128 + c16 * 16);
    }
    cp_commit();
}

// ---------------------------------------------------------------------------
// GEMM kernel: one 128x128 tile per CTA, 8 warps (4M x 2N), warp tile 32x64.
// s8 IMMA m16n8k32, K=256 in 2 chunks of 128B rows, 2 syncs. Epilogue ONCE.
// ---------------------------------------------------------------------------
__global__ void __launch_bounds__(256, 2)
gemm_tile_kernel() {
    extern __shared__ char smraw[];
    const uint32_t sb0   = smem_u32(smraw);
    const uint32_t sbase = (sb0 + 1023) & ~1023u;
    char* smp = smraw + (sbase - sb0);

    uint32_t* rowkey = (uint32_t*)(smp + OFF_KEY);
    int*      cnt    = (int*)     (smp + OFF_CNT);
    int*      cand   = (int*)     (smp + OFF_CAND);

    const int tid  = threadIdx.x;
    const int wid  = tid >> 5;
    const int lane = tid & 31;
    const int m0   = blockIdx.x * MBLK;
    const int n0   = blockIdx.y * NTILE;
    const int wm   = (wid & 3) * 32;
    const int wn   = (wid >> 2) * 64;
    const int lrow = lane & 15;
    const int lcol = (lane >> 4) << 4;
    const int g    = lane >> 2;
    const int tg   = lane & 3;

    // Swizzled row bases; addr(kb) = base ^ kb (kb in swizzle bits 4..6).
    const uint32_t swzA0 = SWZ((uint32_t)((wm + lrow) * 128)) ^ (uint32_t)lcol;
    const uint32_t swzA1 = SWZ((uint32_t)((wm + 16 + lrow) * 128)) ^ (uint32_t)lcol;
    uint32_t swzB[4];
#pragma unroll
    for (int jn = 0; jn < 4; jn++)
        swzB[jn] = SWZ((uint32_t)((wn + jn * 16 + lrow) * 128)) ^ (uint32_t)lcol;

    if (tid < 128) { rowkey[tid] = 0xFFFFFFFFu; cnt[tid] = 0; }

    stage_ab(sbase + OFF_BUF, m0, n0, 0, tid);

    int32_t acc[2][8][4];
#pragma unroll
    for (int a = 0; a < 2; a++)
#pragma unroll
        for (int b = 0; b < 8; b++)
#pragma unroll
            for (int c = 0; c < 4; c++) acc[a][b][c] = 0;

    uint32_t fa0[2][4], fa1[2][4], fb[2][4][4];

#pragma unroll
    for (int kc = 0; kc < N_KC; kc++) {
        cp_wait<0>();
        __syncthreads();
        if (kc + 1 < N_KC)
            stage_ab(sbase + OFF_BUF + ((kc + 1) & 1) * STAGE_BYTES,
                     m0, n0, kc + 1, tid);

        const uint32_t pa = sbase + OFF_BUF + (kc & 1) * STAGE_BYTES;
        const uint32_t pb = pa + 16384;

        // prologue: frags for ks=0 (k-step = 32 s8 dims = 32 bytes)
        ldm_x4(fa0[0][0], fa0[0][1], fa0[0][2], fa0[0][3], pa + swzA0);
        ldm_x4(fa1[0][0], fa1[0][1], fa1[0][2], fa1[0][3], pa + swzA1);
#pragma unroll
        for (int jn = 0; jn < 4; jn++)
            ldm_x4(fb[0][jn][0], fb[0][jn][1], fb[0][jn][2], fb[0][jn][3],
                   pb + swzB[jn]);

#pragma unroll
        for (int ks = 0; ks < 4; ks++) {
            const int cur = ks & 1, nxt = cur ^ 1;
            if (ks < 3) {
                const uint32_t kb = (uint32_t)((ks + 1) * 32);
                ldm_x4(fa0[nxt][0], fa0[nxt][1], fa0[nxt][2], fa0[nxt][3],
                       pa + (swzA0 ^ kb));
                ldm_x4(fa1[nxt][0], fa1[nxt][1], fa1[nxt][2], fa1[nxt][3],
                       pa + (swzA1 ^ kb));
#pragma unroll
                for (int jn = 0; jn < 4; jn++)
                    ldm_x4(fb[nxt][jn][0], fb[nxt][jn][1],
                           fb[nxt][jn][2], fb[nxt][jn][3],
                           pb + (swzB[jn] ^ kb));
            }
#pragma unroll
            for (int jn = 0; jn < 4; jn++) {
                mma_s8(acc[0][jn * 2],     fa0[cur][0], fa0[cur][1], fa0[cur][2], fa0[cur][3], fb[cur][jn][0], fb[cur][jn][2]);
                mma_s8(acc[0][jn * 2 + 1], fa0[cur][0], fa0[cur][1], fa0[cur][2], fa0[cur][3], fb[cur][jn][1], fb[cur][jn][3]);
                mma_s8(acc[1][jn * 2],     fa1[cur][0], fa1[cur][1], fa1[cur][2], fa1[cur][3], fb[cur][jn][0], fb[cur][jn][2]);
                mma_s8(acc[1][jn * 2 + 1], fa1[cur][0], fa1[cur][1], fa1[cur][2], fa1[cur][3], fb[cur][jn][1], fb[cur][jn][3]);
            }
        }
    }

    // ---- Epilogue (once): scale to float score, tile min + candidates ------
    float c2r[8][2], msc[8][2];
#pragma unroll
    for (int jn = 0; jn < 8; jn++)
#pragma unroll
        for (int q = 0; q < 2; q++) {
            int n = n0 + wn + jn * 8 + tg * 2 + q;
            c2r[jn][q] = __ldg(&g_c2[n]);
            msc[jn][q] = -2.f * __ldg(&g_sc[n]);
        }
    float sxr[2][2];
#pragma unroll
    for (int im = 0; im < 2; im++)
#pragma unroll
        for (int h = 0; h < 2; h++)
            sxr[im][h] = __ldg(&g_sx[m0 + wm + im * 16 + h * 8 + g]);

#pragma unroll
    for (int im = 0; im < 2; im++)
#pragma unroll
        for (int h = 0; h < 2; h++) {
            int r = wm + im * 16 + h * 8 + g;
            float mn = 3.4e38f;
#pragma unroll
            for (int jn = 0; jn < 8; jn++)
#pragma unroll
                for (int q = 0; q < 2; q++) {
                    float sc = fmaf(sxr[im][h],
                                    msc[jn][q] * (float)acc[im][jn][h * 2 + q],
                                    c2r[jn][q]);
                    mn = fminf(mn, sc);
                }
            mn = fminf(mn, __shfl_xor_sync(0xffffffffu, mn, 1));
            mn = fminf(mn, __shfl_xor_sync(0xffffffffu, mn, 2));
            if (tg == 0) atomicMin(&rowkey[r], fkey(mn));
        }
    __syncthreads();

#pragma unroll
    for (int im = 0; im < 2; im++)
#pragma unroll
        for (int h = 0; h < 2; h++) {
            int r = wm + im * 16 + h * 8 + g;
            float thr = fdec(rowkey[r]) + MARGIN;
#pragma unroll
            for (int jn = 0; jn < 8; jn++)
#pragma unroll
                for (int q = 0; q < 2; q++) {
                    float sc = fmaf(sxr[im][h],
                                    msc[jn][q] * (float)acc[im][jn][h * 2 + q],
                                    c2r[jn][q]);
                    if (sc < thr) {
                        int p = atomicAdd(&cnt[r], 1);
                        if (p < RCAP)
                            cand[r * RCAP + p] = n0 + wn + jn * 8 + tg * 2 + q;
                    }
                }
        }
    __syncthreads();

    // ---- Write 32B record per row ------------------------------------------
    if (tid < 128) {
        int rec[8];
        rec[0] = __float_as_int(fdec(rowkey[tid]));
        rec[1] = cnt[tid];
#pragma unroll
        for (int j = 0; j < RCAP; j++) rec[2 + j] = cand[tid * RCAP + j];
        int* dst = g_rec + ((size_t)(m0 + tid) * N_TILES + blockIdx.y) * 8;
        *(int4*)(dst)     = make_int4(rec[0], rec[1], rec[2], rec[3]);
        *(int4*)(dst + 4) = make_int4(rec[4], rec[5], rec[6], rec[7]);
    }
}

// ---------------------------------------------------------------------------
// Combine: per token, global min over tiles, exact fp32 rescore of pruned
// candidate set, gather + SSE partial + index. 128 threads per token.
// ---------------------------------------------------------------------------
__global__ void __launch_bounds__(128)
combine_kernel(const float* __restrict__ x, const float* __restrict__ cb,
               float* __restrict__ out_q, float* __restrict__ out_idx) {
    __shared__ int   recs[N_TILES * 8];
    __shared__ float xs[DIM];
    __shared__ float sgmin;
    __shared__ int   clist[N_TILES * RCAP];
    __shared__ int   ftile[N_TILES];
    __shared__ int   ccnt, fcnt;
    __shared__ unsigned long long sbest;

    const int t = blockIdx.x, tid = threadIdx.x;
    const int wid = tid >> 5, lane = tid & 31;

    if (tid < 32) ((int4*)recs)[tid] = ((const int4*)(g_rec + (size_t)t * N_TILES * 8))[tid];
    ((float2*)xs)[tid] = ((const float2*)(x + (size_t)t * DIM))[tid];
    if (tid == 0) { ccnt = 0; fcnt = 0; sbest = ~0ull; }
    __syncthreads();

    if (tid == 0) {
        float gm = 3.4e38f;
#pragma unroll
        for (int i = 0; i < N_TILES; i++)
            gm = fminf(gm, __int_as_float(recs[i * 8]));
        sgmin = gm;
    }
    __syncthreads();
    const float glim = sgmin + MARGIN;

    if (tid < N_TILES) {
        float tmin = __int_as_float(recs[tid * 8]);
        if (tmin <= glim) {
            int c = recs[tid * 8 + 1];
            if (c <= RCAP) {
                for (int j = 0; j < c; j++) {
                    int p = atomicAdd(&ccnt, 1);
                    clist[p] = recs[tid * 8 + 2 + j];
                }
            } else {
                int p = atomicAdd(&fcnt, 1);
                ftile[p] = tid;
            }
        }
    }
    __syncthreads();

    // exact rescore: warp per candidate
    const int nc = ccnt;
    for (int ci = wid; ci < nc; ci += 4) {
        int n = clist[ci];
        const float* cr = cb + (size_t)n * DIM;
        float dot = 0.f;
#pragma unroll
        for (int j = 0; j < 8; j++)
            dot = fmaf(xs[lane + j * 32], cr[lane + j * 32], dot);
#pragma unroll
        for (int o = 16; o > 0; o >>= 1)
            dot += __shfl_xor_sync(0xffffffffu, dot, o);
        if (lane == 0) {
            float sv = __ldg(&g_c2[n]) - 2.f * dot;
            unsigned long long key =
                ((unsigned long long)fkey(sv) << 32) | (uint32_t)n;
            atomicMin(&sbest, key);
        }
    }

    // overflowed tiles (rare): exact rescan of all 128 codes in the tile
    const int nf = fcnt;
    for (int fi = 0; fi < nf; fi++) {
        int base = ftile[fi] * NTILE;
        for (int cc = wid; cc < NTILE; cc += 4) {
            int n = base + cc;
            const float* cr = cb + (size_t)n * DIM;
            float dot = 0.f;
#pragma unroll
            for (int j = 0; j < 8; j++)
                dot = fmaf(xs[lane + j * 32], cr[lane + j * 32], dot);
#pragma unroll
            for (int o = 16; o > 0; o >>= 1)
                dot += __shfl_xor_sync(0xffffffffu, dot, o);
            if (lane == 0) {
                float sv = __ldg(&g_c2[n]) - 2.f * dot;
                unsigned long long key =
                    ((unsigned long long)fkey(sv) << 32) | (uint32_t)n;
                atomicMin(&sbest, key);
            }
        }
    }
    __syncthreads();
    const int best = (int)(sbest & 0xFFFFFFFFull);

    // gather + SSE partial
    float2 c2v = ((const float2*)(cb + (size_t)best * DIM))[tid];
    ((float2*)(out_q + (size_t)t * DIM))[tid] = c2v;
    float2 xv = ((const float2*)xs)[tid];
    float dx = xv.x - c2v.x, dy = xv.y - c2v.y;
    float d = dx * dx + dy * dy;
#pragma unroll
    for (int o = 16; o > 0; o >>= 1) d += __shfl_xor_sync(0xffffffffu, d, o);
    __shared__ float red[4];
    if (lane == 0) red[wid] = d;
    __syncthreads();
    if (tid == 0) {
        g_partial[t] = red[0] + red[1] + red[2] + red[3];
        out_idx[t]   = (float)best;
    }
}

// ---------------------------------------------------------------------------
__global__ void loss_kernel(float* __restrict__ out_loss, int n4, float inv_count) {
    __shared__ float red[32];
    const int tid = threadIdx.x;
    float s = 0.f;
    const float4* p4 = (const float4*)g_partial;
    for (int i = tid; i < n4; i += 1024) {
        float4 v = p4[i];
        s += v.x + v.y + v.z + v.w;
    }
#pragma unroll
    for (int o = 16; o > 0; o >>= 1) s += __shfl_xor_sync(0xffffffffu, s, o);
    if ((tid & 31) == 0) red[tid >> 5] = s;
    __syncthreads();
    if (tid < 32) {
        float v = red[tid];
#pragma unroll
        for (int o = 16; o > 0; o >>= 1) v += __shfl_xor_sync(0xffffffffu, v, o);
        if (tid == 0) *out_loss = 2.f * v * inv_count;
    }
}

// ---------------------------------------------------------------------------
extern "C" void kernel_launch(void* const* d_in, const int* in_sizes, int n_in,
                              void* d_out, int out_size) {
    const float* x  = (const float*)d_in[0];
    const float* cb = (const float*)d_in[1];
    float* out = (float*)d_out;

    const int bt = in_sizes[0] / DIM;   // 32768
    const int nc = in_sizes[1] / DIM;   // 2048

    const long long need = (long long)bt * DIM + bt + 1;
    const bool full_layout = ((long long)out_size >= need);
    float* out_idx  = full_layout ? (out + (size_t)bt * DIM) : g_dummy;
    float* out_loss = full_layout ? (out + (size_t)bt * DIM + bt) : (g_dummy + BT);

    int8_t* xq; cudaGetSymbolAddress((void**)&xq, g_xq);
    int8_t* cq; cudaGetSymbolAddress((void**)&cq, g_cq);
    float* sx;  cudaGetSymbolAddress((void**)&sx, g_sx);
    float* sc;  cudaGetSymbolAddress((void**)&sc, g_sc);

    quant_kernel<<<(bt * 32 + 255) / 256, 256>>>(x,  xq, sx, bt);
    quant_kernel<<<(nc * 32 + 255) / 256, 256>>>(cb, cq, sc, nc);
    c2_kernel<<<(nc + 7) / 8, 256>>>(cb, nc);

    cudaFuncSetAttribute(gemm_tile_kernel,
                         cudaFuncAttributeMaxDynamicSharedMemorySize, SMEM_BYTES);
    dim3 grid(bt / MBLK, nc / NTILE);
    gemm_tile_kernel<<<grid, 256, SMEM_BYTES>>>();

    combine_kernel<<<bt, 128>>>(x, cb, out, out_idx);
    loss_kernel<<<1, 1024>>>(out_loss, bt / 4, 1.f / ((float)bt * (float)DIM));
}

// round 11
// speedup vs baseline: 1.8203x; 1.8203x over previous
#include <cuda_runtime.h>
#include <cuda_bf16.h>
#include <cstdint>

#define DIM     256
#define BT      32768
#define NCODE   2048
#define MARGIN  1.0f
#define RCAP    6                  // candidates per row per tile record
#define MBLK    128
#define NTILE   128
#define N_TILES (NCODE / NTILE)    // 16
#define KC      64                 // dims per K-chunk
#define N_KC    (DIM / KC)         // 4
#define STAGE_BYTES 32768          // A 16KB + B 16KB

// GEMM smem layout (relative to 1KB-aligned base)
#define OFF_BUF  0                 // 2 stages x 32 KB
#define OFF_KEY  65536             // u32[128]
#define OFF_CNT  66048             // int[128]
#define OFF_CAND 66560             // int[128][RCAP] = 3072
#define SMEM_BYTES (66560 + 128 * RCAP * 4 + 1024)

// ---------------------------------------------------------------------------
__device__ __nv_bfloat16 g_xb [(size_t)BT * DIM];      // 16 MB
__device__ __nv_bfloat16 g_cbb[(size_t)NCODE * DIM];   // 1 MB
__device__ float g_c2[NCODE];
__device__ int   g_rec[(size_t)BT * N_TILES * 8];      // 16 MB: {minf,cnt,cand[6]}
__device__ float g_partial[BT];
__device__ float g_dummy[BT + 1];

// ---------------------------------------------------------------------------
__device__ __forceinline__ uint32_t smem_u32(const void* p) {
    uint32_t a;
    asm("{ .reg .u64 t; cvta.to.shared.u64 t, %1; cvt.u32.u64 %0, t; }"
        : "=r"(a) : "l"(p));
    return a;
}

#define SWZ(o) ((o) ^ (((o) >> 3) & 0x70))

__device__ __forceinline__ void cp16(uint32_t d, const void* s) {
    asm volatile("cp.async.cg.shared.global [%0], [%1], 16;\n"
                 :: "r"(d), "l"(__cvta_generic_to_global(s)));
}
__device__ __forceinline__ void cp_commit() {
    asm volatile("cp.async.commit_group;\n" ::: "memory");
}
template <int N> __device__ __forceinline__ void cp_wait() {
    asm volatile("cp.async.wait_group %0;\n" :: "n"(N) : "memory");
}

__device__ __forceinline__ void ldm_x4(uint32_t& r0, uint32_t& r1,
                                       uint32_t& r2, uint32_t& r3, uint32_t a) {
    asm volatile("ldmatrix.sync.aligned.m8n8.x4.shared.b16 {%0,%1,%2,%3}, [%4];"
                 : "=r"(r0), "=r"(r1), "=r"(r2), "=r"(r3) : "r"(a));
}

__device__ __forceinline__ void mma_bf16(float* d, uint32_t a0, uint32_t a1,
                                         uint32_t a2, uint32_t a3,
                                         uint32_t b0, uint32_t b1) {
    asm volatile(
        "mma.sync.aligned.m16n8k16.row.col.f32.bf16.bf16.f32 "
        "{%0,%1,%2,%3}, {%4,%5,%6,%7}, {%8,%9}, {%0,%1,%2,%3};"
        : "+f"(d[0]), "+f"(d[1]), "+f"(d[2]), "+f"(d[3])
        : "r"(a0), "r"(a1), "r"(a2), "r"(a3), "r"(b0), "r"(b1));
}

__device__ __forceinline__ uint32_t fkey(float f) {
    uint32_t u = __float_as_uint(f);
    return (u & 0x80000000u) ? ~u : (u | 0x80000000u);
}
__device__ __forceinline__ float fdec(uint32_t k) {
    uint32_t u = (k & 0x80000000u) ? (k ^ 0x80000000u) : ~k;
    return __uint_as_float(u);
}

// ---------------------------------------------------------------------------
__global__ void tobf16_kernel(const float* __restrict__ in,
                              __nv_bfloat16* __restrict__ outp, int n4) {
    int i = blockIdx.x * blockDim.x + threadIdx.x;
    if (i >= n4) return;
    float4 v = ((const float4*)in)[i];
    ((__nv_bfloat162*)outp)[2 * i]     = __floats2bfloat162_rn(v.x, v.y);
    ((__nv_bfloat162*)outp)[2 * i + 1] = __floats2bfloat162_rn(v.z, v.w);
}

__global__ void c2_kernel(const float* __restrict__ cb, int N) {
    int warp = (blockIdx.x * blockDim.x + threadIdx.x) >> 5;
    int lane = threadIdx.x & 31;
    if (warp >= N) return;
    const float4* row = (const float4*)(cb + (size_t)warp * DIM);
    float s = 0.f;
#pragma unroll
    for (int i = 0; i < 2; i++) {
        float4 v = row[lane + i * 32];
        s += v.x * v.x + v.y * v.y + v.z * v.z + v.w * v.w;
    }
#pragma unroll
    for (int o = 16; o > 0; o >>= 1) s += __shfl_xor_sync(0xffffffffu, s, o);
    if (lane == 0) g_c2[warp] = s;
}

// ---------------------------------------------------------------------------
// stage one K-chunk: A[128 x 64] + B[128 x 64] bf16 (16KB each)
// ---------------------------------------------------------------------------
__device__ __forceinline__ void stage_ab(uint32_t dst, int m0, int n0,
                                         int kc, int tid) {
#pragma unroll
    for (int i = 0; i < 4; i++) {
        int idx = tid + (i << 8);
        int c16 = idx & 7;
        int row = idx >> 3;
        uint32_t off = SWZ((uint32_t)(row * 128 + c16 * 16));
        cp16(dst + off,
             g_xb + (size_t)(m0 + row) * DIM + kc * KC + c16 * 8);
        cp16(dst + 16384 + off,
             g_cbb + (size_t)(n0 + row) * DIM + kc * KC + c16 * 8);
    }
    cp_commit();
}

// ---------------------------------------------------------------------------
// GEMM kernel: one 128x128 tile per CTA, 8 warps (4M x 2N), warp tile 32x64.
// Mainloop: next-ks LDSM hand-interleaved between cur-ks MMAs (asm order is
// preserved, so this forces crossbar/tensor overlap). Epilogue ONCE.
// ---------------------------------------------------------------------------
__global__ void __launch_bounds__(256, 2)
gemm_tile_kernel() {
    extern __shared__ char smraw[];
    const uint32_t sb0   = smem_u32(smraw);
    const uint32_t sbase = (sb0 + 1023) & ~1023u;
    char* smp = smraw + (sbase - sb0);

    uint32_t* rowkey = (uint32_t*)(smp + OFF_KEY);
    int*      cnt    = (int*)     (smp + OFF_CNT);
    int*      cand   = (int*)     (smp + OFF_CAND);

    const int tid  = threadIdx.x;
    const int wid  = tid >> 5;
    const int lane = tid & 31;
    const int m0   = blockIdx.x * MBLK;
    const int n0   = blockIdx.y * NTILE;
    const int wm   = (wid & 3) * 32;
    const int wn   = (wid >> 2) * 64;
    const int lrow = lane & 15;
    const int lcol = (lane >> 4) << 4;
    const int g    = lane >> 2;
    const int tg   = lane & 3;

    // Swizzled row bases. Addr(kb) = base ^ kb (kb hits swizzle bits 4..6).
    const uint32_t swzA0 = SWZ((uint32_t)((wm + lrow) * 128)) ^ (uint32_t)lcol;
    const uint32_t swzA1 = SWZ((uint32_t)((wm + 16 + lrow) * 128)) ^ (uint32_t)lcol;
    uint32_t swzB[4];
#pragma unroll
    for (int jn = 0; jn < 4; jn++)
        swzB[jn] = SWZ((uint32_t)((wn + jn * 16 + lrow) * 128)) ^ (uint32_t)lcol;

    if (tid < 128) { rowkey[tid] = 0xFFFFFFFFu; cnt[tid] = 0; }

    stage_ab(sbase + OFF_BUF, m0, n0, 0, tid);

    float acc[2][8][4];
#pragma unroll
    for (int a = 0; a < 2; a++)
#pragma unroll
        for (int b = 0; b < 8; b++)
#pragma unroll
            for (int c = 0; c < 4; c++) acc[a][b][c] = 0.f;

    uint32_t fa0[2][4], fa1[2][4], fb[2][4][4];

#pragma unroll
    for (int kc = 0; kc < N_KC; kc++) {
        cp_wait<0>();
        __syncthreads();
        if (kc + 1 < N_KC)
            stage_ab(sbase + OFF_BUF + ((kc + 1) & 1) * STAGE_BYTES,
                     m0, n0, kc + 1, tid);

        const uint32_t pa = sbase + OFF_BUF + (kc & 1) * STAGE_BYTES;
        const uint32_t pb = pa + 16384;

        // prologue: frags for ks=0
        ldm_x4(fa0[0][0], fa0[0][1], fa0[0][2], fa0[0][3], pa + swzA0);
        ldm_x4(fa1[0][0], fa1[0][1], fa1[0][2], fa1[0][3], pa + swzA1);
#pragma unroll
        for (int jn = 0; jn < 4; jn++)
            ldm_x4(fb[0][jn][0], fb[0][jn][1], fb[0][jn][2], fb[0][jn][3],
                   pb + swzB[jn]);

#pragma unroll
        for (int ks = 0; ks < 4; ks++) {
            const int cur = ks & 1, nxt = cur ^ 1;
            const uint32_t kb = (uint32_t)((ks + 1) * 32);
            if (ks < 3) {
                // interleaved: 6 next-ks LDSM threaded between 16 cur MMAs
                ldm_x4(fa0[nxt][0], fa0[nxt][1], fa0[nxt][2], fa0[nxt][3],
                       pa + (swzA0 ^ kb));
                mma_bf16(acc[0][0], fa0[cur][0], fa0[cur][1], fa0[cur][2], fa0[cur][3], fb[cur][0][0], fb[cur][0][2]);
                mma_bf16(acc[0][1], fa0[cur][0], fa0[cur][1], fa0[cur][2], fa0[cur][3], fb[cur][0][1], fb[cur][0][3]);

                ldm_x4(fa1[nxt][0], fa1[nxt][1], fa1[nxt][2], fa1[nxt][3],
                       pa + (swzA1 ^ kb));
                mma_bf16(acc[1][0], fa1[cur][0], fa1[cur][1], fa1[cur][2], fa1[cur][3], fb[cur][0][0], fb[cur][0][2]);
                mma_bf16(acc[1][1], fa1[cur][0], fa1[cur][1], fa1[cur][2], fa1[cur][3], fb[cur][0][1], fb[cur][0][3]);

                ldm_x4(fb[nxt][0][0], fb[nxt][0][1], fb[nxt][0][2], fb[nxt][0][3],
                       pb + (swzB[0] ^ kb));
                mma_bf16(acc[0][2], fa0[cur][0], fa0[cur][1], fa0[cur][2], fa0[cur][3], fb[cur][1][0], fb[cur][1][2]);
                mma_bf16(acc[0][3], fa0[cur][0], fa0[cur][1], fa0[cur][2], fa0[cur][3], fb[cur][1][1], fb[cur][1][3]);
                mma_bf16(acc[1][2], fa1[cur][0], fa1[cur][1], fa1[cur][2], fa1[cur][3], fb[cur][1][0], fb[cur][1][2]);

                ldm_x4(fb[nxt][1][0], fb[nxt][1][1], fb[nxt][1][2], fb[nxt][1][3],
                       pb + (swzB[1] ^ kb));
                mma_bf16(acc[1][3], fa1[cur][0], fa1[cur][1], fa1[cur][2], fa1[cur][3], fb[cur][1][1], fb[cur][1][3]);
                mma_bf16(acc[0][4], fa0[cur][0], fa0[cur][1], fa0[cur][2], fa0[cur][3], fb[cur][2][0], fb[cur][2][2]);
                mma_bf16(acc[0][5], fa0[cur][0], fa0[cur][1], fa0[cur][2], fa0[cur][3], fb[cur][2][1], fb[cur][2][3]);

                ldm_x4(fb[nxt][2][0], fb[nxt][2][1], fb[nxt][2][2], fb[nxt][2][3],
                       pb + (swzB[2] ^ kb));
                mma_bf16(acc[1][4], fa1[cur][0], fa1[cur][1], fa1[cur][2], fa1[cur][3], fb[cur][2][0], fb[cur][2][2]);
                mma_bf16(acc[1][5], fa1[cur][0], fa1[cur][1], fa1[cur][2], fa1[cur][3], fb[cur][2][1], fb[cur][2][3]);
                mma_bf16(acc[0][6], fa0[cur][0], fa0[cur][1], fa0[cur][2], fa0[cur][3], fb[cur][3][0], fb[cur][3][2]);

                ldm_x4(fb[nxt][3][0], fb[nxt][3][1], fb[nxt][3][2], fb[nxt][3][3],
                       pb + (swzB[3] ^ kb));
                mma_bf16(acc[0][7], fa0[cur][0], fa0[cur][1], fa0[cur][2], fa0[cur][3], fb[cur][3][1], fb[cur][3][3]);
                mma_bf16(acc[1][6], fa1[cur][0], fa1[cur][1], fa1[cur][2], fa1[cur][3], fb[cur][3][0], fb[cur][3][2]);
                mma_bf16(acc[1][7], fa1[cur][0], fa1[cur][1], fa1[cur][2], fa1[cur][3], fb[cur][3][1], fb[cur][3][3]);
            } else {
#pragma unroll
                for (int jn = 0; jn < 4; jn++) {
                    mma_bf16(acc[0][jn * 2],     fa0[cur][0], fa0[cur][1], fa0[cur][2], fa0[cur][3], fb[cur][jn][0], fb[cur][jn][2]);
                    mma_bf16(acc[0][jn * 2 + 1], fa0[cur][0], fa0[cur][1], fa0[cur][2], fa0[cur][3], fb[cur][jn][1], fb[cur][jn][3]);
                    mma_bf16(acc[1][jn * 2],     fa1[cur][0], fa1[cur][1], fa1[cur][2], fa1[cur][3], fb[cur][jn][0], fb[cur][jn][2]);
                    mma_bf16(acc[1][jn * 2 + 1], fa1[cur][0], fa1[cur][1], fa1[cur][2], fa1[cur][3], fb[cur][jn][1], fb[cur][jn][3]);
                }
            }
        }
    }

    // ---- Epilogue (once): tile-local min + candidates -----------------------
    float c2r[8][2];
#pragma unroll
    for (int jn = 0; jn < 8; jn++)
#pragma unroll
        for (int q = 0; q < 2; q++)
            c2r[jn][q] = __ldg(&g_c2[n0 + wn + jn * 8 + tg * 2 + q]);

#pragma unroll
    for (int im = 0; im < 2; im++)
#pragma unroll
        for (int h = 0; h < 2; h++) {
            int r = wm + im * 16 + h * 8 + g;
            float mn = 3.4e38f;
#pragma unroll
            for (int jn = 0; jn < 8; jn++)
#pragma unroll
                for (int q = 0; q < 2; q++)
                    mn = fminf(mn, fmaf(-2.f, acc[im][jn][h * 2 + q], c2r[jn][q]));
            mn = fminf(mn, __shfl_xor_sync(0xffffffffu, mn, 1));
            mn = fminf(mn, __shfl_xor_sync(0xffffffffu, mn, 2));
            if (tg == 0) atomicMin(&rowkey[r], fkey(mn));
        }
    __syncthreads();

#pragma unroll
    for (int im = 0; im < 2; im++)
#pragma unroll
        for (int h = 0; h < 2; h++) {
            int r = wm + im * 16 + h * 8 + g;
            float thr = fdec(rowkey[r]) + MARGIN;
#pragma unroll
            for (int jn = 0; jn < 8; jn++)
#pragma unroll
                for (int q = 0; q < 2; q++) {
                    float sc = fmaf(-2.f, acc[im][jn][h * 2 + q], c2r[jn][q]);
                    if (sc < thr) {
                        int p = atomicAdd(&cnt[r], 1);
                        if (p < RCAP)
                            cand[r * RCAP + p] = n0 + wn + jn * 8 + tg * 2 + q;
                    }
                }
        }
    __syncthreads();

    // ---- Write 32B record per row ------------------------------------------
    if (tid < 128) {
        int rec[8];
        rec[0] = __float_as_int(fdec(rowkey[tid]));
        rec[1] = cnt[tid];
#pragma unroll
        for (int j = 0; j < RCAP; j++) rec[2 + j] = cand[tid * RCAP + j];
        int* dst = g_rec + ((size_t)(m0 + tid) * N_TILES + blockIdx.y) * 8;
        *(int4*)(dst)     = make_int4(rec[0], rec[1], rec[2], rec[3]);
        *(int4*)(dst + 4) = make_int4(rec[4], rec[5], rec[6], rec[7]);
    }
}

// ---------------------------------------------------------------------------
// Combine: per token, global min over tiles, exact fp32 rescore of pruned
// candidate set, gather + SSE partial + index. 128 threads per token.
// ---------------------------------------------------------------------------
__global__ void __launch_bounds__(128)
combine_kernel(const float* __restrict__ x, const float* __restrict__ cb,
               float* __restrict__ out_q, float* __restrict__ out_idx) {
    __shared__ int   recs[N_TILES * 8];
    __shared__ float xs[DIM];
    __shared__ float sgmin;
    __shared__ int   clist[N_TILES * RCAP];
    __shared__ int   ftile[N_TILES];
    __shared__ int   ccnt, fcnt;
    __shared__ unsigned long long sbest;

    const int t = blockIdx.x, tid = threadIdx.x;
    const int wid = tid >> 5, lane = tid & 31;

    if (tid < 32) ((int4*)recs)[tid] = ((const int4*)(g_rec + (size_t)t * N_TILES * 8))[tid];
    ((float2*)xs)[tid] = ((const float2*)(x + (size_t)t * DIM))[tid];
    if (tid == 0) { ccnt = 0; fcnt = 0; sbest = ~0ull; }
    __syncthreads();

    if (tid == 0) {
        float gm = 3.4e38f;
#pragma unroll
        for (int i = 0; i < N_TILES; i++)
            gm = fminf(gm, __int_as_float(recs[i * 8]));
        sgmin = gm;
    }
    __syncthreads();
    const float glim = sgmin + MARGIN;

    if (tid < N_TILES) {
        float tmin = __int_as_float(recs[tid * 8]);
        if (tmin <= glim) {
            int c = recs[tid * 8 + 1];
            if (c <= RCAP) {
                for (int j = 0; j < c; j++) {
                    int p = atomicAdd(&ccnt, 1);
                    clist[p] = recs[tid * 8 + 2 + j];
                }
            } else {
                int p = atomicAdd(&fcnt, 1);
                ftile[p] = tid;
            }
        }
    }
    __syncthreads();

    // exact rescore: warp per candidate
    const int nc = ccnt;
    for (int ci = wid; ci < nc; ci += 4) {
        int n = clist[ci];
        const float* cr = cb + (size_t)n * DIM;
        float dot = 0.f;
#pragma unroll
        for (int j = 0; j < 8; j++)
            dot = fmaf(xs[lane + j * 32], cr[lane + j * 32], dot);
#pragma unroll
        for (int o = 16; o > 0; o >>= 1)
            dot += __shfl_xor_sync(0xffffffffu, dot, o);
        if (lane == 0) {
            float sv = __ldg(&g_c2[n]) - 2.f * dot;
            unsigned long long key =
                ((unsigned long long)fkey(sv) << 32) | (uint32_t)n;
            atomicMin(&sbest, key);
        }
    }

    // overflowed tiles (rare): exact rescan of all 128 codes in the tile
    const int nf = fcnt;
    for (int fi = 0; fi < nf; fi++) {
        int base = ftile[fi] * NTILE;
        for (int cc = wid; cc < NTILE; cc += 4) {
            int n = base + cc;
            const float* cr = cb + (size_t)n * DIM;
            float dot = 0.f;
#pragma unroll
            for (int j = 0; j < 8; j++)
                dot = fmaf(xs[lane + j * 32], cr[lane + j * 32], dot);
#pragma unroll
            for (int o = 16; o > 0; o >>= 1)
                dot += __shfl_xor_sync(0xffffffffu, dot, o);
            if (lane == 0) {
                float sv = __ldg(&g_c2[n]) - 2.f * dot;
                unsigned long long key =
                    ((unsigned long long)fkey(sv) << 32) | (uint32_t)n;
                atomicMin(&sbest, key);
            }
        }
    }
    __syncthreads();
    const int best = (int)(sbest & 0xFFFFFFFFull);

    // gather + SSE partial
    float2 c2v = ((const float2*)(cb + (size_t)best * DIM))[tid];
    ((float2*)(out_q + (size_t)t * DIM))[tid] = c2v;
    float2 xv = ((const float2*)xs)[tid];
    float dx = xv.x - c2v.x, dy = xv.y - c2v.y;
    float d = dx * dx + dy * dy;
#pragma unroll
    for (int o = 16; o > 0; o >>= 1) d += __shfl_xor_sync(0xffffffffu, d, o);
    __shared__ float red[4];
    if (lane == 0) red[wid] = d;
    __syncthreads();
    if (tid == 0) {
        g_partial[t] = red[0] + red[1] + red[2] + red[3];
        out_idx[t]   = (float)best;
    }
}

// ---------------------------------------------------------------------------
__global__ void loss_kernel(float* __restrict__ out_loss, int n4, float inv_count) {
    __shared__ float red[32];
    const int tid = threadIdx.x;
    float s = 0.f;
    const float4* p4 = (const float4*)g_partial;
    for (int i = tid; i < n4; i += 1024) {
        float4 v = p4[i];
        s += v.x + v.y + v.z + v.w;
    }
#pragma unroll
    for (int o = 16; o > 0; o >>= 1) s += __shfl_xor_sync(0xffffffffu, s, o);
    if ((tid & 31) == 0) red[tid >> 5] = s;
    __syncthreads();
    if (tid < 32) {
        float v = red[tid];
#pragma unroll
        for (int o = 16; o > 0; o >>= 1) v += __shfl_xor_sync(0xffffffffu, v, o);
        if (tid == 0) *out_loss = 2.f * v * inv_count;
    }
}

// ---------------------------------------------------------------------------
extern "C" void kernel_launch(void* const* d_in, const int* in_sizes, int n_in,
                              void* d_out, int out_size) {
    const float* x  = (const float*)d_in[0];
    const float* cb = (const float*)d_in[1];
    float* out = (float*)d_out;

    const int bt = in_sizes[0] / DIM;   // 32768
    const int nc = in_sizes[1] / DIM;   // 2048

    const long long need = (long long)bt * DIM + bt + 1;
    const bool full_layout = ((long long)out_size >= need);
    float* out_idx  = full_layout ? (out + (size_t)bt * DIM) : g_dummy;
    float* out_loss = full_layout ? (out + (size_t)bt * DIM + bt) : (g_dummy + BT);

    __nv_bfloat16* xb;  cudaGetSymbolAddress((void**)&xb,  g_xb);
    __nv_bfloat16* cbb; cudaGetSymbolAddress((void**)&cbb, g_cbb);

    const int nx4 = bt * DIM / 4;
    const int nc4 = nc * DIM / 4;
    tobf16_kernel<<<(nx4 + 255) / 256, 256>>>(x,  xb,  nx4);
    tobf16_kernel<<<(nc4 + 255) / 256, 256>>>(cb, cbb, nc4);
    c2_kernel<<<(nc + 7) / 8, 256>>>(cb, nc);

    cudaFuncSetAttribute(gemm_tile_kernel,
                         cudaFuncAttributeMaxDynamicSharedMemorySize, SMEM_BYTES);
    dim3 grid(bt / MBLK, nc / NTILE);
    gemm_tile_kernel<<<grid, 256, SMEM_BYTES>>>();

    combine_kernel<<<bt, 128>>>(x, cb, out, out_idx);
    loss_kernel<<<1, 1024>>>(out_loss, bt / 4, 1.f / ((float)bt * (float)DIM));
}